// round 5
// baseline (speedup 1.0000x reference)
#include <cuda_runtime.h>
#include <math.h>

#define BATCH 8
#define NA    261888
#define KTOP  6000
#define PROP  1000
#define SHIFT 14
#define NBUCK (1 << 18)
#define CAP   8192
#define SORTN 8192

#define MASKW32 192          /* u32 words per mask row (= 96 u64, 6144 bits) */
#define MASKW64 96

/* ---------------- device scratch (static: no allocation allowed) -------- */
__device__ unsigned int       g_hist[BATCH][NBUCK];
__device__ unsigned int       g_maxbucket[BATCH];
__device__ int                g_thresh[BATCH];
__device__ unsigned int       g_total[BATCH];
__device__ unsigned long long g_cand[BATCH][CAP];
__device__ float4             g_boxes[BATCH * KTOP];
__device__ float              g_areas[BATCH * KTOP];
__device__ unsigned int       g_mask[BATCH][KTOP][MASKW32];   /* ~37 MB */

/* order-preserving float -> uint key */
__device__ __forceinline__ unsigned int fkey(float s) {
    unsigned int u = __float_as_uint(s);
    return u ^ ((unsigned int)((int)u >> 31) | 0x80000000u);
}

/* ---------------- kernel 0: clear scratch ------------------------------ */
__global__ void clear_kernel() {
    size_t tid    = (size_t)blockIdx.x * blockDim.x + threadIdx.x;
    size_t stride = (size_t)gridDim.x * blockDim.x;
    uint4* h4 = (uint4*)&g_hist[0][0];
    size_t n4 = (size_t)BATCH * NBUCK / 4;
    uint4 z4 = make_uint4(0, 0, 0, 0);
    for (size_t i = tid; i < n4; i += stride) h4[i] = z4;
    unsigned long long* c = &g_cand[0][0];
    for (size_t i = tid; i < (size_t)BATCH * CAP; i += stride) c[i] = 0ull;
    if (tid < BATCH) g_maxbucket[tid] = 0u;
}

/* ---------------- kernel 1: per-batch bucket histogram ------------------ */
__global__ void hist_kernel(const float* __restrict__ probs) {
    int b = blockIdx.y;
    const float* p = probs + (size_t)b * NA * 2;
    unsigned int lmax = 0;
    for (int a = blockIdx.x * blockDim.x + threadIdx.x; a < NA;
         a += gridDim.x * blockDim.x) {
        unsigned int key = fkey(p[2 * a + 1]);
        unsigned int bk = key >> SHIFT;
        atomicAdd(&g_hist[b][bk], 1u);
        lmax = max(lmax, bk);
    }
    __shared__ unsigned int sm[256];
    sm[threadIdx.x] = lmax;
    __syncthreads();
    for (int o = 128; o > 0; o >>= 1) {
        if (threadIdx.x < o) sm[threadIdx.x] = max(sm[threadIdx.x], sm[threadIdx.x + o]);
        __syncthreads();
    }
    if (threadIdx.x == 0) atomicMax(&g_maxbucket[b], sm[0]);
}

/* ---------------- kernel 2: find threshold bucket, write fill bases ----- */
__global__ void findthresh_kernel() {
    int b = blockIdx.x, tid = threadIdx.x;
    __shared__ unsigned int scnt[256];
    __shared__ unsigned int s_running;
    if (tid == 0) s_running = 0;
    __syncthreads();
    int start = (int)g_maxbucket[b];
    for (int cs = start; cs >= 0; cs -= 256) {
        int bk = cs - tid;
        unsigned int c = (bk >= 0) ? g_hist[b][bk] : 0u;
        scnt[tid] = c;
        __syncthreads();
        for (int off = 1; off < 256; off <<= 1) {
            unsigned int v = (tid >= off) ? scnt[tid - off] : 0u;
            __syncthreads();
            scnt[tid] += v;
            __syncthreads();
        }
        unsigned int incl = scnt[tid];
        unsigned int excl = incl - c;
        unsigned int run = s_running;
        if (bk >= 0 && run + excl < KTOP) {
            g_hist[b][bk] = run + excl;
            if (run + incl >= KTOP) {
                g_thresh[b] = bk;
                g_total[b]  = run + incl;
            }
        }
        __syncthreads();
        if (tid == 0) s_running = run + scnt[255];
        __syncthreads();
        if (s_running >= KTOP) break;
    }
}

/* ---------------- kernel 3: compact candidates (grouped by bucket) ------ */
__global__ void compact_kernel(const float* __restrict__ probs) {
    int b = blockIdx.y;
    int tb = g_thresh[b];
    const float* p = probs + (size_t)b * NA * 2;
    for (int a = blockIdx.x * blockDim.x + threadIdx.x; a < NA;
         a += gridDim.x * blockDim.x) {
        unsigned int key = fkey(p[2 * a + 1]);
        unsigned int bk = key >> SHIFT;
        if ((int)bk >= tb) {
            unsigned int pos = atomicAdd(&g_hist[b][bk], 1u);
            if (pos < CAP)
                g_cand[b][pos] =
                    ((unsigned long long)key << 32) | (unsigned int)(~a);
        }
    }
}

/* ---------------- kernel 4: bitonic sort + gather + box decode ---------- */
__global__ void __launch_bounds__(1024, 1)
sort_gather_kernel(const float* __restrict__ bbox,
                   const float* __restrict__ anchors) {
    extern __shared__ unsigned long long s[];
    int b = blockIdx.x, tid = threadIdx.x;
    for (int i = tid; i < SORTN; i += blockDim.x) s[i] = g_cand[b][i];
    __syncthreads();
    for (int k = 2; k <= SORTN; k <<= 1) {
        for (int j = k >> 1; j > 0; j >>= 1) {
            for (int i = tid; i < SORTN; i += blockDim.x) {
                int ixj = i ^ j;
                if (ixj > i) {
                    unsigned long long x = s[i], y = s[ixj];
                    bool up = ((i & k) == 0);
                    if (up ? (x < y) : (x > y)) { s[i] = y; s[ixj] = x; }
                }
            }
            __syncthreads();
        }
    }
    const float4* anc = (const float4*)(anchors + (size_t)b * NA * 4);
    const float4* dl  = (const float4*)(bbox    + (size_t)b * NA * 4);
    for (int i = tid; i < KTOP; i += blockDim.x) {
        unsigned int idx = ~(unsigned int)(s[i]);
        float4 a4 = anc[idx];
        float4 r4 = dl[idx];
        float d0 = __fmul_rn(r4.x, 0.1f);
        float d1 = __fmul_rn(r4.y, 0.1f);
        float d2 = __fmul_rn(r4.z, 0.2f);
        float d3 = __fmul_rn(r4.w, 0.2f);
        float h  = __fsub_rn(a4.z, a4.x);
        float w  = __fsub_rn(a4.w, a4.y);
        float cy = __fadd_rn(__fadd_rn(a4.x, __fmul_rn(0.5f, h)), __fmul_rn(d0, h));
        float cx = __fadd_rn(__fadd_rn(a4.y, __fmul_rn(0.5f, w)), __fmul_rn(d1, w));
        float h2 = __fmul_rn(h, expf(d2));
        float w2 = __fmul_rn(w, expf(d3));
        float y1 = __fsub_rn(cy, __fmul_rn(0.5f, h2));
        float x1 = __fsub_rn(cx, __fmul_rn(0.5f, w2));
        float y2 = __fadd_rn(y1, h2);
        float x2 = __fadd_rn(x1, w2);
        y1 = fminf(fmaxf(y1, 0.0f), 1.0f);
        x1 = fminf(fmaxf(x1, 0.0f), 1.0f);
        y2 = fminf(fmaxf(y2, 0.0f), 1.0f);
        x2 = fminf(fmaxf(x2, 0.0f), 1.0f);
        g_boxes[b * KTOP + i] = make_float4(y1, x1, y2, x2);
        g_areas[b * KTOP + i] = __fmul_rn(__fsub_rn(y2, y1), __fsub_rn(x2, x1));
    }
}

/* ------- kernel 5: suppression-mask build (8 rows/warp, reg-reuse) ------ */
#define MBK_THREADS 256
#define MBK_RPW     8                  /* rows per warp */
#define MBK_ROWS    (8 * MBK_RPW)      /* 64 rows per block */
#define MBK_CHUNK   2048

__global__ void __launch_bounds__(MBK_THREADS)
mask_build_kernel() {
    int b       = blockIdx.y;
    int rowbase = blockIdx.x * MBK_ROWS;
    int warp    = threadIdx.x >> 5;
    int lane    = threadIdx.x & 31;
    int i0      = rowbase + warp * MBK_RPW;   /* warp's first row */

    __shared__ float4 sbox[MBK_CHUNK];
    __shared__ float  sarea[MBK_CHUNK];

    const float4* boxes = g_boxes + b * KTOP;
    const float*  areas = g_areas + b * KTOP;

    /* row boxes in registers */
    float4 rb[MBK_RPW]; float ra[MBK_RPW];
#pragma unroll
    for (int r = 0; r < MBK_RPW; ++r) {
        int i = i0 + r;
        if (i < KTOP) { rb[r] = boxes[i]; ra[r] = areas[i]; }
        else { rb[r] = make_float4(0.f, 0.f, 0.f, 0.f); ra[r] = 0.f; }
    }

    for (int chunk = 0; chunk < KTOP; chunk += MBK_CHUNK) {
        int cn = min(MBK_CHUNK, KTOP - chunk);
        if (chunk + cn <= rowbase) continue;        /* block-uniform */
        __syncthreads();
        for (int t = threadIdx.x; t < cn; t += MBK_THREADS) {
            sbox[t]  = boxes[chunk + t];
            sarea[t] = areas[chunk + t];
        }
        /* zero-pad tail to a word multiple */
        int cnw = (cn + 31) & ~31;
        for (int t = cn + threadIdx.x; t < cnw; t += MBK_THREADS) {
            sbox[t]  = make_float4(2.f, 2.f, 2.f, 2.f);  /* no overlap w/ clipped */
            sarea[t] = 0.f;
        }
        __syncthreads();

        int wstart = (i0 > chunk) ? ((i0 - chunk) >> 5) : 0;
        int wend   = cnw >> 5;
        for (int wd = wstart; wd < wend; ++wd) {
            int j = chunk + wd * 32 + lane;
            float4 cbx = sbox[wd * 32 + lane];
            float  cax = sarea[wd * 32 + lane];
            bool   jok = (j < KTOP);
            unsigned int myword = 0;
#pragma unroll
            for (int r = 0; r < MBK_RPW; ++r) {
                float yy1 = fmaxf(rb[r].x, cbx.x);
                float xx1 = fmaxf(rb[r].y, cbx.y);
                float yy2 = fminf(rb[r].z, cbx.z);
                float xx2 = fminf(rb[r].w, cbx.w);
                float inter = __fmul_rn(fmaxf(__fsub_rn(yy2, yy1), 0.0f),
                                        fmaxf(__fsub_rn(xx2, xx1), 0.0f));
                bool sup = false;
                if (inter > 0.0f) {       /* inter>0 => union>0 (tiny boxes) */
                    float uni = __fsub_rn(__fadd_rn(ra[r], cax), inter);
                    if (uni > 0.0f)
                        sup = !(__fdiv_rn(inter, uni) <= 0.7f);
                }
                unsigned int w = __ballot_sync(0xFFFFFFFFu, sup && jok);
                if (lane == r) myword = w;
            }
            if (lane < MBK_RPW && (i0 + lane) < KTOP)
                g_mask[b][i0 + lane][(chunk >> 5) + wd] = myword;
        }
    }
}

/* ------- kernel 6: warp-serial greedy pass, 8-wide speculative ---------- */
__global__ void __launch_bounds__(32, 1)
nms_serial_kernel(float* __restrict__ out) {
    int b    = blockIdx.x;
    int lane = threadIdx.x;
    __shared__ int s_picks[PROP];
    __shared__ int s_cand[8];
    __shared__ unsigned int s_sup[8];
    __shared__ int s_acc, s_step, s_fill;

    /* valid bitmap: u64 word wu = g*32 + lane covers bits [wu*64, wu*64+63] */
    unsigned long long V[3];
#pragma unroll
    for (int g = 0; g < 3; ++g) {
        int wu = g * 32 + lane;
        V[g] = (wu < 93) ? ~0ull
             : (wu == 93) ? ((1ull << 48) - 1ull) : 0ull;
    }

    const unsigned long long* mask64 =
        (const unsigned long long*)&g_mask[b][0][0];

    if (lane == 0) s_fill = -1;
    __syncwarp();
    int step = 0;
    int done_fill = -1;

    while (step < PROP) {
        /* ---- packed popcount scan: 3 fields in one u64 ---- */
        unsigned long long packed =
              (unsigned long long)__popcll(V[0])
            | ((unsigned long long)__popcll(V[1]) << 21)
            | ((unsigned long long)__popcll(V[2]) << 42);
        unsigned long long inc = packed;
#pragma unroll
        for (int off = 1; off < 32; off <<= 1) {
            unsigned long long t = __shfl_up_sync(0xFFFFFFFFu, inc, off);
            if (lane >= off) inc += t;
        }
        unsigned long long tots = __shfl_sync(0xFFFFFFFFu, inc, 31);
        unsigned long long exc  = inc - packed;
        int e0 = (int)(exc & 0x1FFFFF);
        int e1 = (int)((exc >> 21) & 0x1FFFFF);
        int e2 = (int)(exc >> 42);
        int t0 = (int)(tots & 0x1FFFFF);
        int t1 = (int)((tots >> 21) & 0x1FFFFF);
        int t2 = (int)(tots >> 42);
        int navail = t0 + t1 + t2;
        if (navail > 8) navail = 8;
        if (navail == 0) break;

        /* ---- extract first <=8 set bits by global rank ---- */
        {
            unsigned long long v = V[0]; int rk = e0;
            while (v && rk < 8) {
                s_cand[rk] = lane * 64 + (__ffsll((long long)v) - 1);
                v &= v - 1ull; rk++;
            }
            v = V[1]; rk = t0 + e1;
            while (v && rk < 8) {
                s_cand[rk] = 2048 + lane * 64 + (__ffsll((long long)v) - 1);
                v &= v - 1ull; rk++;
            }
            v = V[2]; rk = t0 + t1 + e2;
            while (v && rk < 8) {
                s_cand[rk] = 4096 + lane * 64 + (__ffsll((long long)v) - 1);
                v &= v - 1ull; rk++;
            }
        }
        __syncwarp();

        /* ---- load the 8 candidate mask rows (one L2 round trip) ---- */
        unsigned long long m[8][3];
        int cnd[8];
#pragma unroll
        for (int t = 0; t < 8; ++t) {
            if (t < navail) {
                cnd[t] = s_cand[t];
                const unsigned long long* row = mask64 + (size_t)cnd[t] * MASKW64;
                m[t][0] = row[lane];
                m[t][1] = row[lane + 32];
                m[t][2] = row[lane + 64];
            } else {
                cnd[t] = -1;
                m[t][0] = m[t][1] = m[t][2] = 0ull;
            }
        }

        /* ---- owner lanes build 8-bit suppressed-by-s bytes locally ---- */
#pragma unroll
        for (int t = 0; t < 8; ++t) {
            if (t < navail) {
                int c = cnd[t];
                int wdi = c >> 6;
                if ((wdi & 31) == lane) {
                    int g = wdi >> 5, bidx = c & 63;
                    unsigned int byte = 0;
#pragma unroll
                    for (int s = 0; s < 8; ++s) {
                        unsigned long long w =
                            (g == 0) ? m[s][0] : (g == 1) ? m[s][1] : m[s][2];
                        byte |= (unsigned int)((w >> bidx) & 1ull) << s;
                    }
                    s_sup[t] = byte;
                }
            }
        }
        __syncwarp();

        /* ---- lane 0 resolves greedy acceptance ---- */
        if (lane == 0) {
            int acc = 0, sp = step;
            for (int t = 0; t < navail && sp < PROP; ++t) {
                if ((s_sup[t] & (unsigned int)acc) == 0u) {
                    acc |= 1 << t;
                    s_picks[sp++] = s_cand[t];
                    if (((s_sup[t] >> t) & 1u) == 0u) {  /* degenerate */
                        s_fill = s_cand[t];
                        break;
                    }
                }
            }
            s_acc = acc; s_step = sp;
        }
        __syncwarp();
        int acc = s_acc;
        step = s_step;
        done_fill = s_fill;
#pragma unroll
        for (int t = 0; t < 8; ++t) {
            if (acc & (1 << t)) {
                V[0] &= ~m[t][0]; V[1] &= ~m[t][1]; V[2] &= ~m[t][2];
            }
        }
        if (done_fill >= 0) break;
    }

    /* ---- fill remainder + output gather ---- */
    for (int s2 = step + lane; s2 < PROP; s2 += 32) s_picks[s2] = done_fill;
    __syncwarp();
    const float4* boxes = g_boxes + b * KTOP;
    float4* o = (float4*)out + b * PROP;
    for (int s2 = lane; s2 < PROP; s2 += 32) {
        int p = s_picks[s2];
        o[s2] = (p >= 0) ? boxes[p] : make_float4(0.f, 0.f, 0.f, 0.f);
    }
}

/* ---------------- launch ------------------------------------------------ */
extern "C" void kernel_launch(void* const* d_in, const int* in_sizes, int n_in,
                              void* d_out, int out_size) {
    const float* probs   = (const float*)d_in[0];  /* (B, A, 2) */
    const float* bbox    = (const float*)d_in[1];  /* (B, A, 4) */
    const float* anchors = (const float*)d_in[2];  /* (B, A, 4) */
    float* out = (float*)d_out;                    /* (B, 1000, 4) */

    cudaFuncSetAttribute(sort_gather_kernel,
                         cudaFuncAttributeMaxDynamicSharedMemorySize, SORTN * 8);

    clear_kernel<<<1024, 256>>>();
    dim3 hg(256, BATCH);
    hist_kernel<<<hg, 256>>>(probs);
    findthresh_kernel<<<BATCH, 256>>>();
    compact_kernel<<<hg, 256>>>(probs);
    sort_gather_kernel<<<BATCH, 1024, SORTN * 8>>>(bbox, anchors);
    dim3 mg((KTOP + MBK_ROWS - 1) / MBK_ROWS, BATCH);
    mask_build_kernel<<<mg, MBK_THREADS>>>();
    nms_serial_kernel<<<BATCH, 32>>>(out);
}